// round 15
// baseline (speedup 1.0000x reference)
#include <cuda_runtime.h>
#include <cuda_bf16.h>
#include <cstdint>
#include <math.h>

#define SELU_A 1.6732632423543772f
#define SELU_S 1.0507009873554805f

#define NLINKS_MAX 100000
#define NEDGES_MAX 1600000
#define SENT 0x7FFFFFFF

// ---------------- scratch (no allocations allowed) ----------------
__device__ float g_LS0[NLINKS_MAX * 64];
__device__ float g_LS1[NLINKS_MAX * 64];
__device__ float g_PQ [NLINKS_MAX * 128];
__device__ float g_gemb[256 * 64];
__device__ float g_r1 [256 * 256];
__device__ float g_r2 [256 * 256];
// W_gcn as per-lane mma B-fragments: [((kt*4+ntp)*2+img)*32 + lane] -> uint4
// uint4 = {reg0_ntileEven, reg1_ntileEven, reg0_ntileOdd, reg1_ntileOdd}
__device__ uint4 g_Bfrag[1024];          // 16KB, L1-resident
__device__ uint4 g_B2h[1088];            // W_msg combined hi, [64 k][136 j] bf16
__device__ uint4 g_B2l[1088];            // W_msg combined lo
// sort scratch
__device__ int g_cnt[NLINKS_MAX + 1];
__device__ int g_cur[NLINKS_MAX + 1];
__device__ int g_blk[512];
__device__ int g_sf[NEDGES_MAX];
__device__ int g_ss[NEDGES_MAX];

// ---------------- generic helpers ----------------
__device__ __forceinline__ float selu_f(float x) {
    return x > 0.f ? SELU_S * x : SELU_S * SELU_A * (__expf(x) - 1.f);
}
__device__ __forceinline__ void red2(float* p, float a, float b) {
    asm volatile("red.global.add.v2.f32 [%0], {%1,%2};"
                 :: "l"(p), "f"(a), "f"(b) : "memory");
}
__device__ __forceinline__ uint32_t smem_u32(const void* p) {
    uint32_t a;
    asm("{ .reg .u64 t; cvta.to.shared.u64 t, %1; cvt.u32.u64 %0, t; }" : "=r"(a) : "l"(p));
    return a;
}

// ---------------- warp MMA helpers ----------------
__device__ __forceinline__ void ldsm_x4(uint32_t* r, uint32_t addr) {
    asm volatile("ldmatrix.sync.aligned.m8n8.x4.shared.b16 {%0,%1,%2,%3}, [%4];"
                 : "=r"(r[0]), "=r"(r[1]), "=r"(r[2]), "=r"(r[3]) : "r"(addr));
}
__device__ __forceinline__ void ldsm_x4_t(uint32_t* r, uint32_t addr) {
    asm volatile("ldmatrix.sync.aligned.m8n8.x4.trans.shared.b16 {%0,%1,%2,%3}, [%4];"
                 : "=r"(r[0]), "=r"(r[1]), "=r"(r[2]), "=r"(r[3]) : "r"(addr));
}
__device__ __forceinline__ void mma_bf16(float* c, const uint32_t* a, uint32_t b0, uint32_t b1) {
    asm volatile("mma.sync.aligned.m16n8k16.row.col.f32.bf16.bf16.f32 "
                 "{%0,%1,%2,%3}, {%4,%5,%6,%7}, {%8,%9}, {%0,%1,%2,%3};"
                 : "+f"(c[0]), "+f"(c[1]), "+f"(c[2]), "+f"(c[3])
                 : "r"(a[0]), "r"(a[1]), "r"(a[2]), "r"(a[3]), "r"(b0), "r"(b1));
}

// vectorized bf16 split
__device__ __forceinline__ void split_pack2(float a, float b, uint32_t& hi, uint32_t& lo) {
    asm("cvt.rn.satfinite.bf16x2.f32 %0, %1, %2;" : "=r"(hi) : "f"(b), "f"(a));
    float ah = __uint_as_float(hi << 16);
    float bh = __uint_as_float(hi & 0xffff0000u);
    float ra = a - ah;
    float rb = b - bh;
    asm("cvt.rn.satfinite.bf16x2.f32 %0, %1, %2;" : "=r"(lo) : "f"(rb), "f"(ra));
}

// smem layout for edge kernel (bytes). 128 edges/block, 8 warps, M=16/warp.
// No B in smem (B frags come from the global 16KB image via L1).
#define OFF_AH   0
#define OFF_AL   18432
#define OFF_SS   36864
#define SMEM_EDGE 37376
#define C_STRIDE 68
// C (f32, stride 68) aliases Ah/Al after MMA: 128*68*4 = 34816 <= 36864

// smem layout for pq kernel
#define PQ_AH  0
#define PQ_AL  18432
#define PQ_BH  36864
#define PQ_BL  54272
#define SMEM_PQMMA 71680

// ============================================================================
// counting sort of edges by `second`
// ============================================================================
__global__ void hist_kernel(const int* __restrict__ snd, int E) {
    int e = blockIdx.x * blockDim.x + threadIdx.x;
    if (e < E) atomicAdd(&g_cnt[snd[e]], 1);
}

#define SCAN_B 256
__global__ void scan1_kernel(int n) {
    __shared__ int wsum[8];
    int b = blockIdx.x, t = threadIdx.x;
    int i = b * SCAN_B + t;
    int v = (i < n) ? g_cnt[i] : 0;
    int x = v;
    #pragma unroll
    for (int o = 1; o < 32; o <<= 1) {
        int y = __shfl_up_sync(0xffffffffu, x, o);
        if ((t & 31) >= o) x += y;
    }
    if ((t & 31) == 31) wsum[t >> 5] = x;
    __syncthreads();
    if (t < 8) {
        int y = wsum[t];
        #pragma unroll
        for (int o = 1; o < 8; o <<= 1) {
            int z = __shfl_up_sync(0xffu, y, o);
            if (t >= o) y += z;
        }
        wsum[t] = y;
    }
    __syncthreads();
    int base = (t >= 32) ? wsum[(t >> 5) - 1] : 0;
    if (i < n) g_cnt[i] = base + x - v;
    if (t == SCAN_B - 1) g_blk[b] = base + x;
}

__global__ void scan2_kernel(int nb) {
    __shared__ int s[512];
    int t = threadIdx.x;
    s[t] = (t < nb) ? g_blk[t] : 0;
    __syncthreads();
    for (int o = 1; o < 512; o <<= 1) {
        int v = (t >= o) ? s[t - o] : 0;
        __syncthreads();
        s[t] += v;
        __syncthreads();
    }
    if (t < nb) g_blk[t] = (t == 0) ? 0 : s[t - 1];
}

__global__ void scan3_kernel(int n) {
    int i = blockIdx.x * SCAN_B + threadIdx.x;
    if (i < n) g_cur[i] = g_cnt[i] + g_blk[blockIdx.x];
}

__global__ void scatter_sort_kernel(const int* __restrict__ fst,
                                    const int* __restrict__ snd, int E) {
    int e = blockIdx.x * blockDim.x + threadIdx.x;
    if (e < E) {
        int s = snd[e];
        int p = atomicAdd(&g_cur[s], 1);
        g_sf[p] = fst[e];
        g_ss[p] = s;
    }
}

// ============================================================================
// prep: Wm hi/lo image + W_gcn mma B-fragment image in one launch.
// blocks 0-15: W_msg (8192 elems); blocks 16-17: B fragments (1024 slots)
// ============================================================================
__device__ __forceinline__ unsigned short wg_part(const float* Wg, int k, int n, int img) {
    float w = Wg[k * 64 + n];
    __nv_bfloat16 h = __float2bfloat16_rn(w);
    if (img == 0) return *(unsigned short*)&h;
    float r = w - __bfloat162float(h);
    __nv_bfloat16 l = __float2bfloat16_rn(r);
    return *(unsigned short*)&l;
}

__global__ void prep_w_kernel(const float* __restrict__ Wg, const float* __restrict__ Wm)
{
    int b = blockIdx.x;
    if (b < 16) {
        int idx = b * 512 + threadIdx.x;
        if (idx >= 8192) return;
        int k = idx >> 7, j = idx & 127;
        float w = Wm[(k + ((j >= 64) ? 64 : 0)) * 64 + (j & 63)];
        __nv_bfloat16 h = __float2bfloat16_rn(w);
        float r = w - __bfloat162float(h);
        __nv_bfloat16 l = __float2bfloat16_rn(r);
        ((__nv_bfloat16*)g_B2h)[k * 136 + j] = h;
        ((__nv_bfloat16*)g_B2l)[k * 136 + j] = l;
    } else {
        int idx = (b - 16) * 512 + threadIdx.x;
        if (idx >= 1024) return;
        int l = idx & 31;
        int rest = idx >> 5;
        int img = rest & 1, ntp = (rest >> 1) & 3, kt = rest >> 3;
        int k0 = kt * 16 + (l & 3) * 2;
        int n_e = (ntp * 2) * 8 + (l >> 2);
        int n_o = n_e + 8;
        uint32_t x = (uint32_t)wg_part(Wg, k0,     n_e, img) | ((uint32_t)wg_part(Wg, k0 + 1, n_e, img) << 16);
        uint32_t y = (uint32_t)wg_part(Wg, k0 + 8, n_e, img) | ((uint32_t)wg_part(Wg, k0 + 9, n_e, img) << 16);
        uint32_t z = (uint32_t)wg_part(Wg, k0,     n_o, img) | ((uint32_t)wg_part(Wg, k0 + 1, n_o, img) << 16);
        uint32_t w4= (uint32_t)wg_part(Wg, k0 + 8, n_o, img) | ((uint32_t)wg_part(Wg, k0 + 9, n_o, img) << 16);
        g_Bfrag[((kt * 4 + ntp) * 2 + img) * 32 + l] = make_uint4(x, y, z, w4);
    }
}

// ============================================================================
// PQ kernel (HMMA): PQ[i][0:128] = LS[i] @ [Wm[:64] | Wm[64:]]
// Also zeroes NS via grid-stride stores (overlaps with staging/MMA).
// ============================================================================
__global__ void __launch_bounds__(256) pq_hmma_kernel(const float* __restrict__ LS,
                                                      float* __restrict__ PQ,
                                                      float* __restrict__ NSZ, int N)
{
    extern __shared__ __align__(16) char smc[];
    uint32_t sb = smem_u32(smc);
    int tid = threadIdx.x;
    int w = tid >> 5, l = tid & 31;
    int row0 = blockIdx.x * 128;

    // ---- zero NS slice ----
    {
        uint4 z = make_uint4(0u, 0u, 0u, 0u);
        uint4* p = (uint4*)NSZ;
        size_t total = (size_t)N * 16;
        size_t stride = (size_t)gridDim.x * 256;
        for (size_t i = (size_t)blockIdx.x * 256 + tid; i < total; i += stride)
            p[i] = z;
    }

    {
        uint4* dH = (uint4*)(smc + PQ_BH);
        uint4* dL = (uint4*)(smc + PQ_BL);
        #pragma unroll
        for (int i = 0; i < 4; ++i) {
            dH[tid + 256 * i] = g_B2h[tid + 256 * i];
            dL[tid + 256 * i] = g_B2l[tid + 256 * i];
        }
        if (tid < 64) { dH[1024 + tid] = g_B2h[1024 + tid]; dL[1024 + tid] = g_B2l[1024 + tid]; }
    }

    {
        int r = tid >> 1, h = tid & 1;
        int row = row0 + r;
        const float4* src = (const float4*)(LS + (size_t)row * 64 + h * 32);
        char* rowH = smc + PQ_AH + r * 144 + h * 64;
        char* rowL = smc + PQ_AL + r * 144 + h * 64;
        #pragma unroll
        for (int i = 0; i < 8; ++i) {
            float4 v = (row < N) ? src[i] : make_float4(0.f, 0.f, 0.f, 0.f);
            uint2 vh, vl;
            split_pack2(v.x, v.y, vh.x, vl.x);
            split_pack2(v.z, v.w, vh.y, vl.y);
            *(uint2*)(rowH + i * 8) = vh;
            *(uint2*)(rowL + i * 8) = vl;
        }
    }
    __syncthreads();

    int wm = w & 3, wn = w >> 2;
    float c[2][8][4];
    #pragma unroll
    for (int mt = 0; mt < 2; ++mt)
        #pragma unroll
        for (int nt = 0; nt < 8; ++nt)
            #pragma unroll
            for (int i = 0; i < 4; ++i) c[mt][nt][i] = 0.f;

    int rA = wm * 32 + (l & 15);
    int cA = (l >> 4) * 8;

    #pragma unroll
    for (int kt = 0; kt < 4; ++kt) {
        int K0 = kt * 16;
        uint32_t ah[2][4], al[2][4];
        #pragma unroll
        for (int mt = 0; mt < 2; ++mt) {
            uint32_t aoff = (uint32_t)((rA + mt * 16) * 144 + (K0 + cA) * 2);
            ldsm_x4(ah[mt], sb + PQ_AH + aoff);
            ldsm_x4(al[mt], sb + PQ_AL + aoff);
        }
        int rB = K0 + (l & 15);
        #pragma unroll
        for (int ntp = 0; ntp < 4; ++ntp) {
            uint32_t boff = (uint32_t)(rB * 272 + (wn * 64 + ntp * 16 + cA) * 2);
            uint32_t bh[4], bl[4];
            ldsm_x4_t(bh, sb + PQ_BH + boff);
            ldsm_x4_t(bl, sb + PQ_BL + boff);
            #pragma unroll
            for (int mt = 0; mt < 2; ++mt) {
                mma_bf16(c[mt][2*ntp],   ah[mt], bh[0], bh[1]);
                mma_bf16(c[mt][2*ntp+1], ah[mt], bh[2], bh[3]);
                mma_bf16(c[mt][2*ntp],   ah[mt], bl[0], bl[1]);
                mma_bf16(c[mt][2*ntp+1], ah[mt], bl[2], bl[3]);
                mma_bf16(c[mt][2*ntp],   al[mt], bh[0], bh[1]);
                mma_bf16(c[mt][2*ntp+1], al[mt], bh[2], bh[3]);
            }
        }
    }

    {
        int g = l >> 2, t = l & 3;
        #pragma unroll
        for (int mt = 0; mt < 2; ++mt) {
            int r0 = row0 + wm * 32 + mt * 16 + g;
            #pragma unroll
            for (int nt = 0; nt < 8; ++nt) {
                int col = wn * 64 + nt * 8 + 2 * t;
                if (r0 < N)
                    *(float2*)(PQ + (size_t)r0 * 128 + col) = make_float2(c[mt][nt][0], c[mt][nt][1]);
                if (r0 + 8 < N)
                    *(float2*)(PQ + (size_t)(r0 + 8) * 128 + col) = make_float2(c[mt][nt][2], c[mt][nt][3]);
            }
        }
    }
}

// ============================================================================
// Edge kernel: 128 edges/block, 8 warps, M=16/warp, B frags from global
// (16KB L1-resident) -> smem 37.4KB -> 5 CTAs/SM (40 warps). Reg cap 51 via
// launch_bounds; B-frag loads sequenced (bh then bl) to keep peak regs low.
// ============================================================================
__global__ void __launch_bounds__(256, 5) edge_mma_kernel(
    const float* __restrict__ PQ, const int* __restrict__ sf,
    const int* __restrict__ ss, const float* __restrict__ bmsg,
    const float* __restrict__ bgcn, float* __restrict__ NS, int E)
{
    extern __shared__ __align__(16) char smc[];
    uint32_t sb = smem_u32(smc);
    int* ss_sh = (int*)(smc + OFF_SS);
    int tid = threadIdx.x;
    int w = tid >> 5, l = tid & 31;
    int half = l >> 4, lane16 = l & 15;

    long eb = (long)blockIdx.x * 128;

    // warp w owns edges [w*16, w*16+16); lanes 0-15 hold indices (16-31 dup)
    long myE = eb + w * 16 + lane16;
    bool myV = myE < E;
    int fR = myV ? sf[myE] : 0;
    int sR = myV ? ss[myE] : SENT;
    if (l < 16) ss_sh[w * 16 + l] = sR;

    // ---- cooperative gather: 16 edges/warp, 2 batches of 4 ----
    {
        const float4* PQ4 = (const float4*)PQ;
        float4 bmv = ((const float4*)bmsg)[lane16];
        #pragma unroll
        for (int ii = 0; ii < 8; ii += 4) {
            float4 pv[4], qv[4];
            bool evs[4];
            #pragma unroll
            for (int j = 0; j < 4; ++j) {
                int e2 = 2 * (ii + j) + half;
                int f_e = __shfl_sync(0xffffffffu, fR, e2);
                int s_e = __shfl_sync(0xffffffffu, sR, e2);
                bool ev = s_e != SENT;
                evs[j] = ev;
                if (ev) {
                    pv[j] = PQ4[(size_t)f_e * 32 + lane16];
                    qv[j] = PQ4[(size_t)s_e * 32 + 16 + lane16];
                } else {
                    pv[j] = make_float4(0.f,0.f,0.f,0.f);
                    qv[j] = pv[j];
                }
            }
            #pragma unroll
            for (int j = 0; j < 4; ++j) {
                int e2 = 2 * (ii + j) + half;
                bool ev = evs[j];
                float m0 = ev ? selu_f(pv[j].x + qv[j].x + bmv.x) : 0.f;
                float m1 = ev ? selu_f(pv[j].y + qv[j].y + bmv.y) : 0.f;
                float m2 = ev ? selu_f(pv[j].z + qv[j].z + bmv.z) : 0.f;
                float m3 = ev ? selu_f(pv[j].w + qv[j].w + bmv.w) : 0.f;
                uint2 vh, vl;
                split_pack2(m0, m1, vh.x, vl.x);
                split_pack2(m2, m3, vh.y, vl.y);
                int row = w * 16 + e2;
                *(uint2*)(smc + OFF_AH + row * 144 + lane16 * 8) = vh;
                *(uint2*)(smc + OFF_AL + row * 144 + lane16 * 8) = vl;
            }
        }
    }
    __syncthreads();

    // ---- MMA mainloop: M=16 rows per warp, N=64, K=64; B frags from global ----
    float c[8][4];
    #pragma unroll
    for (int nt = 0; nt < 8; ++nt)
        #pragma unroll
        for (int i = 0; i < 4; ++i) c[nt][i] = 0.f;

    int rA = w * 16 + (l & 15);
    int cA = (l >> 4) * 8;

    #pragma unroll
    for (int kt = 0; kt < 4; ++kt) {
        int K0 = kt * 16;
        uint32_t ah[4], al[4];
        uint32_t aoff = (uint32_t)(rA * 144 + (K0 + cA) * 2);
        ldsm_x4(ah, sb + OFF_AH + aoff);
        ldsm_x4(al, sb + OFF_AL + aoff);
        #pragma unroll
        for (int ntp = 0; ntp < 4; ++ntp) {
            // bh first: Ah*Bh + Al*Bh
            {
                uint4 bh4 = g_Bfrag[((kt * 4 + ntp) * 2 + 0) * 32 + l];
                mma_bf16(c[2*ntp],   ah, bh4.x, bh4.y);
                mma_bf16(c[2*ntp+1], ah, bh4.z, bh4.w);
                mma_bf16(c[2*ntp],   al, bh4.x, bh4.y);
                mma_bf16(c[2*ntp+1], al, bh4.z, bh4.w);
            }
            // bl second: Ah*Bl
            {
                uint4 bl4 = g_Bfrag[((kt * 4 + ntp) * 2 + 1) * 32 + l];
                mma_bf16(c[2*ntp],   ah, bl4.x, bl4.y);
                mma_bf16(c[2*ntp+1], ah, bl4.z, bl4.w);
            }
        }
    }
    __syncthreads();   // all A reads done; safe to alias C over A region

    // ---- bias + relu, C -> smem (stride 68 f32) ----
    {
        float* Cs = (float*)smc;
        int g = l >> 2, t = l & 3;
        int r0 = w * 16 + g;
        #pragma unroll
        for (int nt = 0; nt < 8; ++nt) {
            int col = nt * 8 + 2 * t;
            float2 bgv = *(const float2*)(bgcn + col);
            float2 v0, v1;
            v0.x = fmaxf(c[nt][0] + bgv.x, 0.f);
            v0.y = fmaxf(c[nt][1] + bgv.y, 0.f);
            v1.x = fmaxf(c[nt][2] + bgv.x, 0.f);
            v1.y = fmaxf(c[nt][3] + bgv.y, 0.f);
            *(float2*)(Cs + (size_t)r0 * C_STRIDE + col)       = v0;
            *(float2*)(Cs + (size_t)(r0 + 8) * C_STRIDE + col) = v1;
        }
    }
    __syncthreads();

    // ---- segmented reduction over sorted destinations (16 rows/warp) ----
    {
        const float* Cs = (const float*)smc;
        int c0 = l * 2;
        int rbeg = w * 16, rend = rbeg + 16;
        float2 acc = make_float2(0.f, 0.f);
        int cur = ss_sh[rbeg];
        for (int r = rbeg; r < rend; ++r) {
            int sv = ss_sh[r];
            if (sv != cur) {
                if (cur != SENT) red2(NS + (size_t)cur * 64 + c0, acc.x, acc.y);
                acc = make_float2(0.f, 0.f);
                cur = sv;
            }
            float2 v = *(const float2*)(Cs + (size_t)r * C_STRIDE + c0);
            acc.x += v.x; acc.y += v.y;
        }
        if (cur != SENT) red2(NS + (size_t)cur * 64 + c0, acc.x, acc.y);
    }
}

// ============================================================================
// Readout
// ============================================================================
__device__ __forceinline__ int lower_bound_i(const int* a, int n, int v) {
    int lo = 0, hi = n;
    while (lo < hi) { int m = (lo + hi) >> 1; if (a[m] < v) lo = m + 1; else hi = m; }
    return lo;
}

__global__ void gemb_kernel(const float* __restrict__ LS, const int* __restrict__ gid,
                            float* __restrict__ gemb, int N)
{
    __shared__ float red[4][64];
    int g = blockIdx.x;
    int c = threadIdx.x & 63, part = threadIdx.x >> 6;
    int lo = lower_bound_i(gid, N, g);
    int hi = lower_bound_i(gid, N, g + 1);
    float s = 0.f;
    for (int i = lo + part; i < hi; i += 4) s += LS[(size_t)i * 64 + c];
    red[part][c] = s;
    __syncthreads();
    if (part == 0)
        gemb[g * 64 + c] = red[0][c] + red[1][c] + red[2][c] + red[3][c];
}

__global__ void r1_kernel(const float* __restrict__ ge, const float* __restrict__ W,
                          const float* __restrict__ b, float* __restrict__ out)
{
    __shared__ float xs[64];
    int g = blockIdx.x, j = threadIdx.x;   // 256 threads
    if (j < 64) xs[j] = ge[g * 64 + j];
    __syncthreads();
    float acc = b[j];
    #pragma unroll 8
    for (int k = 0; k < 64; ++k) acc += xs[k] * W[k * 256 + j];
    out[g * 256 + j] = selu_f(acc);
}

__global__ void r2_kernel(const float* __restrict__ r1, const float* __restrict__ W,
                          const float* __restrict__ b, float* __restrict__ out)
{
    __shared__ float xs[256];
    int g = blockIdx.x, j = threadIdx.x;   // 256 threads
    xs[j] = r1[g * 256 + j];
    __syncthreads();
    float acc = b[j];
    #pragma unroll 8
    for (int k = 0; k < 256; ++k) acc += xs[k] * W[k * 256 + j];
    out[g * 256 + j] = selu_f(acc);
}

__global__ void r3_kernel(const float* __restrict__ r2, const float* __restrict__ W,
                          const float* __restrict__ b, float* __restrict__ out)
{
    __shared__ float red[8];
    int g = blockIdx.x, t = threadIdx.x;   // 256 threads
    float v = r2[g * 256 + t] * W[t];
    #pragma unroll
    for (int o = 16; o > 0; o >>= 1) v += __shfl_down_sync(0xffffffffu, v, o);
    if ((t & 31) == 0) red[t >> 5] = v;
    __syncthreads();
    if (t == 0) {
        float s = 0.f;
        #pragma unroll
        for (int i = 0; i < 8; ++i) s += red[i];
        out[g] = s + b[0];
    }
}

// ============================================================================
// Launch
// ============================================================================
extern "C" void kernel_launch(void* const* d_in, const int* in_sizes, int n_in,
                              void* d_out, int out_size)
{
    const float* x    = (const float*)d_in[0];
    const float* Wm   = (const float*)d_in[1];
    const float* bm   = (const float*)d_in[2];
    const float* Wg   = (const float*)d_in[3];
    const float* bg   = (const float*)d_in[4];
    const float* Wr1  = (const float*)d_in[5];
    const float* br1  = (const float*)d_in[6];
    const float* Wr2  = (const float*)d_in[7];
    const float* br2  = (const float*)d_in[8];
    const float* Wr3  = (const float*)d_in[9];
    const float* br3  = (const float*)d_in[10];
    const int*   gid  = (const int*)d_in[11];
    const int*   fst  = (const int*)d_in[12];
    const int*   snd  = (const int*)d_in[13];

    int N = in_sizes[0] / 64;
    int E = in_sizes[12];
    int G = out_size;

    float *ls0, *ls1, *pq, *ge, *r1b, *r2b;
    int *sf, *ss, *cnt;
    cudaGetSymbolAddress((void**)&ls0, g_LS0);
    cudaGetSymbolAddress((void**)&ls1, g_LS1);
    cudaGetSymbolAddress((void**)&pq,  g_PQ);
    cudaGetSymbolAddress((void**)&ge,  g_gemb);
    cudaGetSymbolAddress((void**)&r1b, g_r1);
    cudaGetSymbolAddress((void**)&r2b, g_r2);
    cudaGetSymbolAddress((void**)&sf,  g_sf);
    cudaGetSymbolAddress((void**)&ss,  g_ss);
    cudaGetSymbolAddress((void**)&cnt, g_cnt);

    cudaFuncSetAttribute(pq_hmma_kernel, cudaFuncAttributeMaxDynamicSharedMemorySize, SMEM_PQMMA);
    cudaFuncSetAttribute(edge_mma_kernel, cudaFuncAttributeMaxDynamicSharedMemorySize, SMEM_EDGE);

    // one-time per launch: prep W images + counting sort of edges by dest
    prep_w_kernel<<<18, 512>>>(Wg, Wm);
    cudaMemsetAsync(cnt, 0, (size_t)(N + 1) * sizeof(int));
    hist_kernel<<<(E + 255) / 256, 256>>>(snd, E);
    int nb = (N + SCAN_B - 1) / SCAN_B;
    scan1_kernel<<<nb, SCAN_B>>>(N);
    scan2_kernel<<<1, 512>>>(nb);
    scan3_kernel<<<nb, SCAN_B>>>(N);
    scatter_sort_kernel<<<(E + 255) / 256, 256>>>(fst, snd, E);

    const float* src = x;
    float* bufs[2] = { ls0, ls1 };
    for (int t = 0; t < 4; ++t) {
        float* dst = bufs[t & 1];
        pq_hmma_kernel<<<(N + 127) / 128, 256, SMEM_PQMMA>>>(src, pq, dst, N);
        edge_mma_kernel<<<(E + 127) / 128, 256, SMEM_EDGE>>>(pq, sf, ss, bm, bg, dst, E);
        src = dst;
    }

    gemb_kernel<<<G, 256>>>(src, gid, ge, N);
    r1_kernel<<<G, 256>>>(ge, Wr1, br1, r1b);
    r2_kernel<<<G, 256>>>(r1b, Wr2, br2, r2b);
    r3_kernel<<<G, 256>>>(r2b, Wr3, br3, (float*)d_out);
}

// round 16
// speedup vs baseline: 1.2127x; 1.2127x over previous
#include <cuda_runtime.h>
#include <cuda_bf16.h>
#include <cstdint>
#include <math.h>

#define SELU_A 1.6732632423543772f
#define SELU_S 1.0507009873554805f

#define NLINKS_MAX 100000
#define NEDGES_MAX 1600000
#define SENT 0x7FFFFFFF

// ---------------- scratch (no allocations allowed) ----------------
__device__ float g_LS0[NLINKS_MAX * 64];
__device__ float g_LS1[NLINKS_MAX * 64];
__device__ float g_PQ [NLINKS_MAX * 128];
__device__ float g_gemb[256 * 64];
__device__ float g_r1 [256 * 256];
__device__ float g_r2 [256 * 256];
__device__ uint4 g_Bhp[576];    // W_gcn^T hi, padded [64 k][72 n] bf16
__device__ uint4 g_Blp[576];    // W_gcn^T lo
__device__ uint4 g_B2h[1088];   // W_msg combined hi, [64 k][136 j] bf16
__device__ uint4 g_B2l[1088];   // W_msg combined lo
// sort scratch
__device__ int g_cnt[NLINKS_MAX + 1];
__device__ int g_cur[NLINKS_MAX + 1];
__device__ int g_blk[512];
__device__ int g_sf[NEDGES_MAX];
__device__ int g_ss[NEDGES_MAX];

// ---------------- generic helpers ----------------
__device__ __forceinline__ float selu_f(float x) {
    return x > 0.f ? SELU_S * x : SELU_S * SELU_A * (__expf(x) - 1.f);
}
__device__ __forceinline__ void red2(float* p, float a, float b) {
    asm volatile("red.global.add.v2.f32 [%0], {%1,%2};"
                 :: "l"(p), "f"(a), "f"(b) : "memory");
}
__device__ __forceinline__ uint32_t smem_u32(const void* p) {
    uint32_t a;
    asm("{ .reg .u64 t; cvta.to.shared.u64 t, %1; cvt.u32.u64 %0, t; }" : "=r"(a) : "l"(p));
    return a;
}

// ---------------- warp MMA helpers ----------------
__device__ __forceinline__ void ldsm_x4(uint32_t* r, uint32_t addr) {
    asm volatile("ldmatrix.sync.aligned.m8n8.x4.shared.b16 {%0,%1,%2,%3}, [%4];"
                 : "=r"(r[0]), "=r"(r[1]), "=r"(r[2]), "=r"(r[3]) : "r"(addr));
}
__device__ __forceinline__ void ldsm_x4_t(uint32_t* r, uint32_t addr) {
    asm volatile("ldmatrix.sync.aligned.m8n8.x4.trans.shared.b16 {%0,%1,%2,%3}, [%4];"
                 : "=r"(r[0]), "=r"(r[1]), "=r"(r[2]), "=r"(r[3]) : "r"(addr));
}
__device__ __forceinline__ void mma_bf16(float* c, const uint32_t* a, uint32_t b0, uint32_t b1) {
    asm volatile("mma.sync.aligned.m16n8k16.row.col.f32.bf16.bf16.f32 "
                 "{%0,%1,%2,%3}, {%4,%5,%6,%7}, {%8,%9}, {%0,%1,%2,%3};"
                 : "+f"(c[0]), "+f"(c[1]), "+f"(c[2]), "+f"(c[3])
                 : "r"(a[0]), "r"(a[1]), "r"(a[2]), "r"(a[3]), "r"(b0), "r"(b1));
}

// vectorized bf16 split
__device__ __forceinline__ void split_pack2(float a, float b, uint32_t& hi, uint32_t& lo) {
    asm("cvt.rn.satfinite.bf16x2.f32 %0, %1, %2;" : "=r"(hi) : "f"(b), "f"(a));
    float ah = __uint_as_float(hi << 16);
    float bh = __uint_as_float(hi & 0xffff0000u);
    float ra = a - ah;
    float rb = b - bh;
    asm("cvt.rn.satfinite.bf16x2.f32 %0, %1, %2;" : "=r"(lo) : "f"(rb), "f"(ra));
}

// smem layout for edge kernel (bytes). 128 edges/block, 8 warps, M=16/warp.
#define OFF_AH   0
#define OFF_AL   18432
#define OFF_BH   36864
#define OFF_BL   46080
#define OFF_SS   55296
#define SMEM_EDGE 55808
// per-warp C (16 rows x 68 f32, 272B/row) aliases the warp's OWN A slices:
// rows 0-7 over its Ah slice (w*2304, 8*272=2176<=2304), rows 8-15 over its
// Al slice. All C traffic is warp-local -> __syncwarp ordering suffices.
__device__ __forceinline__ uint32_t crow_off(int w, int r) {
    return (r < 8) ? (uint32_t)(OFF_AH + w * 2304 + r * 272)
                   : (uint32_t)(OFF_AL + w * 2304 + (r - 8) * 272);
}

// smem layout for pq kernel
#define PQ_AH  0
#define PQ_AL  18432
#define PQ_BH  36864
#define PQ_BL  54272
#define SMEM_PQMMA 71680

// ============================================================================
// counting sort of edges by `second`
// ============================================================================
__global__ void hist_kernel(const int* __restrict__ snd, int E) {
    int e = blockIdx.x * blockDim.x + threadIdx.x;
    if (e < E) atomicAdd(&g_cnt[snd[e]], 1);
}

#define SCAN_B 256
__global__ void scan1_kernel(int n) {
    __shared__ int wsum[8];
    int b = blockIdx.x, t = threadIdx.x;
    int i = b * SCAN_B + t;
    int v = (i < n) ? g_cnt[i] : 0;
    int x = v;
    #pragma unroll
    for (int o = 1; o < 32; o <<= 1) {
        int y = __shfl_up_sync(0xffffffffu, x, o);
        if ((t & 31) >= o) x += y;
    }
    if ((t & 31) == 31) wsum[t >> 5] = x;
    __syncthreads();
    if (t < 8) {
        int y = wsum[t];
        #pragma unroll
        for (int o = 1; o < 8; o <<= 1) {
            int z = __shfl_up_sync(0xffu, y, o);
            if (t >= o) y += z;
        }
        wsum[t] = y;
    }
    __syncthreads();
    int base = (t >= 32) ? wsum[(t >> 5) - 1] : 0;
    if (i < n) g_cnt[i] = base + x - v;
    if (t == SCAN_B - 1) g_blk[b] = base + x;
}

__global__ void scan2_kernel(int nb) {
    __shared__ int s[512];
    int t = threadIdx.x;
    s[t] = (t < nb) ? g_blk[t] : 0;
    __syncthreads();
    for (int o = 1; o < 512; o <<= 1) {
        int v = (t >= o) ? s[t - o] : 0;
        __syncthreads();
        s[t] += v;
        __syncthreads();
    }
    if (t < nb) g_blk[t] = (t == 0) ? 0 : s[t - 1];
}

__global__ void scan3_kernel(int n) {
    int i = blockIdx.x * SCAN_B + threadIdx.x;
    if (i < n) g_cur[i] = g_cnt[i] + g_blk[blockIdx.x];
}

__global__ void scatter_sort_kernel(const int* __restrict__ fst,
                                    const int* __restrict__ snd, int E) {
    int e = blockIdx.x * blockDim.x + threadIdx.x;
    if (e < E) {
        int s = snd[e];
        int p = atomicAdd(&g_cur[s], 1);
        g_sf[p] = fst[e];
        g_ss[p] = s;
    }
}

// ============================================================================
// prep: both weight images in one launch (24 blocks x 512)
// ============================================================================
__global__ void prep_w_kernel(const float* __restrict__ Wg, const float* __restrict__ Wm)
{
    int b = blockIdx.x;
    if (b < 8) {
        int idx = b * 512 + threadIdx.x;
        if (idx >= 4096) return;
        int k = idx >> 6, n = idx & 63;
        float w = Wg[k * 64 + n];
        __nv_bfloat16 h = __float2bfloat16_rn(w);
        float r = w - __bfloat162float(h);
        __nv_bfloat16 l = __float2bfloat16_rn(r);
        ((__nv_bfloat16*)g_Bhp)[k * 72 + n] = h;
        ((__nv_bfloat16*)g_Blp)[k * 72 + n] = l;
    } else {
        int idx = (b - 8) * 512 + threadIdx.x;
        if (idx >= 8192) return;
        int k = idx >> 7, j = idx & 127;
        float w = Wm[(k + ((j >= 64) ? 64 : 0)) * 64 + (j & 63)];
        __nv_bfloat16 h = __float2bfloat16_rn(w);
        float r = w - __bfloat162float(h);
        __nv_bfloat16 l = __float2bfloat16_rn(r);
        ((__nv_bfloat16*)g_B2h)[k * 136 + j] = h;
        ((__nv_bfloat16*)g_B2l)[k * 136 + j] = l;
    }
}

// ============================================================================
// PQ kernel (HMMA): PQ[i][0:128] = LS[i] @ [Wm[:64] | Wm[64:]]
// Also zeroes NS via grid-stride stores (overlaps with staging/MMA).
// ============================================================================
__global__ void __launch_bounds__(256) pq_hmma_kernel(const float* __restrict__ LS,
                                                      float* __restrict__ PQ,
                                                      float* __restrict__ NSZ, int N)
{
    extern __shared__ __align__(16) char smc[];
    uint32_t sb = smem_u32(smc);
    int tid = threadIdx.x;
    int w = tid >> 5, l = tid & 31;
    int row0 = blockIdx.x * 128;

    // ---- zero NS slice ----
    {
        uint4 z = make_uint4(0u, 0u, 0u, 0u);
        uint4* p = (uint4*)NSZ;
        size_t total = (size_t)N * 16;
        size_t stride = (size_t)gridDim.x * 256;
        for (size_t i = (size_t)blockIdx.x * 256 + tid; i < total; i += stride)
            p[i] = z;
    }

    {
        uint4* dH = (uint4*)(smc + PQ_BH);
        uint4* dL = (uint4*)(smc + PQ_BL);
        #pragma unroll
        for (int i = 0; i < 4; ++i) {
            dH[tid + 256 * i] = g_B2h[tid + 256 * i];
            dL[tid + 256 * i] = g_B2l[tid + 256 * i];
        }
        if (tid < 64) { dH[1024 + tid] = g_B2h[1024 + tid]; dL[1024 + tid] = g_B2l[1024 + tid]; }
    }

    {
        int r = tid >> 1, h = tid & 1;
        int row = row0 + r;
        const float4* src = (const float4*)(LS + (size_t)row * 64 + h * 32);
        char* rowH = smc + PQ_AH + r * 144 + h * 64;
        char* rowL = smc + PQ_AL + r * 144 + h * 64;
        #pragma unroll
        for (int i = 0; i < 8; ++i) {
            float4 v = (row < N) ? src[i] : make_float4(0.f, 0.f, 0.f, 0.f);
            uint2 vh, vl;
            split_pack2(v.x, v.y, vh.x, vl.x);
            split_pack2(v.z, v.w, vh.y, vl.y);
            *(uint2*)(rowH + i * 8) = vh;
            *(uint2*)(rowL + i * 8) = vl;
        }
    }
    __syncthreads();

    int wm = w & 3, wn = w >> 2;
    float c[2][8][4];
    #pragma unroll
    for (int mt = 0; mt < 2; ++mt)
        #pragma unroll
        for (int nt = 0; nt < 8; ++nt)
            #pragma unroll
            for (int i = 0; i < 4; ++i) c[mt][nt][i] = 0.f;

    int rA = wm * 32 + (l & 15);
    int cA = (l >> 4) * 8;

    #pragma unroll
    for (int kt = 0; kt < 4; ++kt) {
        int K0 = kt * 16;
        uint32_t ah[2][4], al[2][4];
        #pragma unroll
        for (int mt = 0; mt < 2; ++mt) {
            uint32_t aoff = (uint32_t)((rA + mt * 16) * 144 + (K0 + cA) * 2);
            ldsm_x4(ah[mt], sb + PQ_AH + aoff);
            ldsm_x4(al[mt], sb + PQ_AL + aoff);
        }
        int rB = K0 + (l & 15);
        #pragma unroll
        for (int ntp = 0; ntp < 4; ++ntp) {
            uint32_t boff = (uint32_t)(rB * 272 + (wn * 64 + ntp * 16 + cA) * 2);
            uint32_t bh[4], bl[4];
            ldsm_x4_t(bh, sb + PQ_BH + boff);
            ldsm_x4_t(bl, sb + PQ_BL + boff);
            #pragma unroll
            for (int mt = 0; mt < 2; ++mt) {
                mma_bf16(c[mt][2*ntp],   ah[mt], bh[0], bh[1]);
                mma_bf16(c[mt][2*ntp+1], ah[mt], bh[2], bh[3]);
                mma_bf16(c[mt][2*ntp],   ah[mt], bl[0], bl[1]);
                mma_bf16(c[mt][2*ntp+1], ah[mt], bl[2], bl[3]);
                mma_bf16(c[mt][2*ntp],   al[mt], bh[0], bh[1]);
                mma_bf16(c[mt][2*ntp+1], al[mt], bh[2], bh[3]);
            }
        }
    }

    {
        int g = l >> 2, t = l & 3;
        #pragma unroll
        for (int mt = 0; mt < 2; ++mt) {
            int r0 = row0 + wm * 32 + mt * 16 + g;
            #pragma unroll
            for (int nt = 0; nt < 8; ++nt) {
                int col = wn * 64 + nt * 8 + 2 * t;
                if (r0 < N)
                    *(float2*)(PQ + (size_t)r0 * 128 + col) = make_float2(c[mt][nt][0], c[mt][nt][1]);
                if (r0 + 8 < N)
                    *(float2*)(PQ + (size_t)(r0 + 8) * 128 + col) = make_float2(c[mt][nt][2], c[mt][nt][3]);
            }
        }
    }
}

// ============================================================================
// Edge kernel: R14 structure (128 edges/block, 8 warps, M=16/warp, 4 CTAs/SM,
// B in smem), with WARP-LOCAL C aliasing -> post-staging barriers become
// __syncwarp (gather/MMA/epilogue/reduction touch only warp-owned smem).
// ============================================================================
__global__ void __launch_bounds__(256, 4) edge_mma_kernel(
    const float* __restrict__ PQ, const int* __restrict__ sf,
    const int* __restrict__ ss, const float* __restrict__ bmsg,
    const float* __restrict__ bgcn, float* __restrict__ NS, int E)
{
    extern __shared__ __align__(16) char smc[];
    uint32_t sb = smem_u32(smc);
    int* ss_sh = (int*)(smc + OFF_SS);
    int tid = threadIdx.x;
    int w = tid >> 5, l = tid & 31;
    int half = l >> 4, lane16 = l & 15;

    long eb = (long)blockIdx.x * 128;

    // warp w owns edges [w*16, w*16+16); lanes 0-15 hold indices (16-31 dup)
    long myE = eb + w * 16 + lane16;
    bool myV = myE < E;
    int fR = myV ? sf[myE] : 0;
    int sR = myV ? ss[myE] : SENT;
    if (l < 16) ss_sh[w * 16 + l] = sR;

    // ---- stage B (9216B x2) — only block-wide barrier follows ----
    {
        uint4* dH = (uint4*)(smc + OFF_BH);
        uint4* dL = (uint4*)(smc + OFF_BL);
        #pragma unroll
        for (int i = 0; i < 2; ++i) {
            dH[tid + 256 * i] = g_Bhp[tid + 256 * i];
            dL[tid + 256 * i] = g_Blp[tid + 256 * i];
        }
        if (tid < 64) { dH[512 + tid] = g_Bhp[512 + tid]; dL[512 + tid] = g_Blp[512 + tid]; }
    }
    __syncthreads();

    // ---- cooperative gather: 16 edges/warp, 2 batches of 4 (warp-local A) ----
    {
        const float4* PQ4 = (const float4*)PQ;
        float4 bmv = ((const float4*)bmsg)[lane16];
        #pragma unroll
        for (int ii = 0; ii < 8; ii += 4) {
            float4 pv[4], qv[4];
            bool evs[4];
            #pragma unroll
            for (int j = 0; j < 4; ++j) {
                int e2 = 2 * (ii + j) + half;
                int f_e = __shfl_sync(0xffffffffu, fR, e2);
                int s_e = __shfl_sync(0xffffffffu, sR, e2);
                bool ev = s_e != SENT;
                evs[j] = ev;
                if (ev) {
                    pv[j] = PQ4[(size_t)f_e * 32 + lane16];
                    qv[j] = PQ4[(size_t)s_e * 32 + 16 + lane16];
                } else {
                    pv[j] = make_float4(0.f,0.f,0.f,0.f);
                    qv[j] = pv[j];
                }
            }
            #pragma unroll
            for (int j = 0; j < 4; ++j) {
                int e2 = 2 * (ii + j) + half;
                bool ev = evs[j];
                float m0 = ev ? selu_f(pv[j].x + qv[j].x + bmv.x) : 0.f;
                float m1 = ev ? selu_f(pv[j].y + qv[j].y + bmv.y) : 0.f;
                float m2 = ev ? selu_f(pv[j].z + qv[j].z + bmv.z) : 0.f;
                float m3 = ev ? selu_f(pv[j].w + qv[j].w + bmv.w) : 0.f;
                uint2 vh, vl;
                split_pack2(m0, m1, vh.x, vl.x);
                split_pack2(m2, m3, vh.y, vl.y);
                int row = w * 16 + e2;
                *(uint2*)(smc + OFF_AH + row * 144 + lane16 * 8) = vh;
                *(uint2*)(smc + OFF_AL + row * 144 + lane16 * 8) = vl;
            }
        }
    }
    __syncwarp();   // warp's A rows ready for its own ldsm

    // ---- MMA mainloop: M=16 rows per warp, N=64, K=64 ----
    float c[8][4];
    #pragma unroll
    for (int nt = 0; nt < 8; ++nt)
        #pragma unroll
        for (int i = 0; i < 4; ++i) c[nt][i] = 0.f;

    int rA = w * 16 + (l & 15);
    int cA = (l >> 4) * 8;

    #pragma unroll
    for (int kt = 0; kt < 4; ++kt) {
        int K0 = kt * 16;
        uint32_t ah[4], al[4];
        uint32_t aoff = (uint32_t)(rA * 144 + (K0 + cA) * 2);
        ldsm_x4(ah, sb + OFF_AH + aoff);
        ldsm_x4(al, sb + OFF_AL + aoff);
        int rB = K0 + (l & 15);
        #pragma unroll
        for (int ntp = 0; ntp < 4; ++ntp) {
            uint32_t boff = (uint32_t)(rB * 144 + (ntp * 16 + cA) * 2);
            uint32_t bh[4], bl[4];
            ldsm_x4_t(bh, sb + OFF_BH + boff);
            ldsm_x4_t(bl, sb + OFF_BL + boff);
            mma_bf16(c[2*ntp],   ah, bh[0], bh[1]);
            mma_bf16(c[2*ntp+1], ah, bh[2], bh[3]);
            mma_bf16(c[2*ntp],   ah, bl[0], bl[1]);
            mma_bf16(c[2*ntp+1], ah, bl[2], bl[3]);
            mma_bf16(c[2*ntp],   al, bh[0], bh[1]);
            mma_bf16(c[2*ntp+1], al, bh[2], bh[3]);
        }
    }
    __syncwarp();   // warp's A reads done; C aliases only THIS warp's A slices

    // ---- bias + relu, C -> warp-local smem (272B rows over own A slices) ----
    {
        int g = l >> 2, t = l & 3;
        uint32_t rowA = crow_off(w, g);
        uint32_t rowB = crow_off(w, g + 8);
        #pragma unroll
        for (int nt = 0; nt < 8; ++nt) {
            int col = nt * 8 + 2 * t;
            float2 bgv = *(const float2*)(bgcn + col);
            float2 v0, v1;
            v0.x = fmaxf(c[nt][0] + bgv.x, 0.f);
            v0.y = fmaxf(c[nt][1] + bgv.y, 0.f);
            v1.x = fmaxf(c[nt][2] + bgv.x, 0.f);
            v1.y = fmaxf(c[nt][3] + bgv.y, 0.f);
            *(float2*)(smc + rowA + col * 4) = v0;
            *(float2*)(smc + rowB + col * 4) = v1;
        }
    }
    __syncwarp();

    // ---- segmented reduction over sorted destinations (16 rows/warp) ----
    {
        int c0 = l * 2;
        float2 acc = make_float2(0.f, 0.f);
        int cur = ss_sh[w * 16];
        #pragma unroll 4
        for (int r = 0; r < 16; ++r) {
            int sv = ss_sh[w * 16 + r];
            if (sv != cur) {
                if (cur != SENT) red2(NS + (size_t)cur * 64 + c0, acc.x, acc.y);
                acc = make_float2(0.f, 0.f);
                cur = sv;
            }
            float2 v = *(const float2*)(smc + crow_off(w, r) + c0 * 4);
            acc.x += v.x; acc.y += v.y;
        }
        if (cur != SENT) red2(NS + (size_t)cur * 64 + c0, acc.x, acc.y);
    }
}

// ============================================================================
// Readout
// ============================================================================
__device__ __forceinline__ int lower_bound_i(const int* a, int n, int v) {
    int lo = 0, hi = n;
    while (lo < hi) { int m = (lo + hi) >> 1; if (a[m] < v) lo = m + 1; else hi = m; }
    return lo;
}

__global__ void gemb_kernel(const float* __restrict__ LS, const int* __restrict__ gid,
                            float* __restrict__ gemb, int N)
{
    __shared__ float red[4][64];
    int g = blockIdx.x;
    int c = threadIdx.x & 63, part = threadIdx.x >> 6;
    int lo = lower_bound_i(gid, N, g);
    int hi = lower_bound_i(gid, N, g + 1);
    float s = 0.f;
    for (int i = lo + part; i < hi; i += 4) s += LS[(size_t)i * 64 + c];
    red[part][c] = s;
    __syncthreads();
    if (part == 0)
        gemb[g * 64 + c] = red[0][c] + red[1][c] + red[2][c] + red[3][c];
}

__global__ void r1_kernel(const float* __restrict__ ge, const float* __restrict__ W,
                          const float* __restrict__ b, float* __restrict__ out)
{
    __shared__ float xs[64];
    int g = blockIdx.x, j = threadIdx.x;   // 256 threads
    if (j < 64) xs[j] = ge[g * 64 + j];
    __syncthreads();
    float acc = b[j];
    #pragma unroll 8
    for (int k = 0; k < 64; ++k) acc += xs[k] * W[k * 256 + j];
    out[g * 256 + j] = selu_f(acc);
}

__global__ void r2_kernel(const float* __restrict__ r1, const float* __restrict__ W,
                          const float* __restrict__ b, float* __restrict__ out)
{
    __shared__ float xs[256];
    int g = blockIdx.x, j = threadIdx.x;   // 256 threads
    xs[j] = r1[g * 256 + j];
    __syncthreads();
    float acc = b[j];
    #pragma unroll 8
    for (int k = 0; k < 256; ++k) acc += xs[k] * W[k * 256 + j];
    out[g * 256 + j] = selu_f(acc);
}

__global__ void r3_kernel(const float* __restrict__ r2, const float* __restrict__ W,
                          const float* __restrict__ b, float* __restrict__ out)
{
    __shared__ float red[8];
    int g = blockIdx.x, t = threadIdx.x;   // 256 threads
    float v = r2[g * 256 + t] * W[t];
    #pragma unroll
    for (int o = 16; o > 0; o >>= 1) v += __shfl_down_sync(0xffffffffu, v, o);
    if ((t & 31) == 0) red[t >> 5] = v;
    __syncthreads();
    if (t == 0) {
        float s = 0.f;
        #pragma unroll
        for (int i = 0; i < 8; ++i) s += red[i];
        out[g] = s + b[0];
    }
}

// ============================================================================
// Launch
// ============================================================================
extern "C" void kernel_launch(void* const* d_in, const int* in_sizes, int n_in,
                              void* d_out, int out_size)
{
    const float* x    = (const float*)d_in[0];
    const float* Wm   = (const float*)d_in[1];
    const float* bm   = (const float*)d_in[2];
    const float* Wg   = (const float*)d_in[3];
    const float* bg   = (const float*)d_in[4];
    const float* Wr1  = (const float*)d_in[5];
    const float* br1  = (const float*)d_in[6];
    const float* Wr2  = (const float*)d_in[7];
    const float* br2  = (const float*)d_in[8];
    const float* Wr3  = (const float*)d_in[9];
    const float* br3  = (const float*)d_in[10];
    const int*   gid  = (const int*)d_in[11];
    const int*   fst  = (const int*)d_in[12];
    const int*   snd  = (const int*)d_in[13];

    int N = in_sizes[0] / 64;
    int E = in_sizes[12];
    int G = out_size;

    float *ls0, *ls1, *pq, *ge, *r1b, *r2b;
    int *sf, *ss, *cnt;
    cudaGetSymbolAddress((void**)&ls0, g_LS0);
    cudaGetSymbolAddress((void**)&ls1, g_LS1);
    cudaGetSymbolAddress((void**)&pq,  g_PQ);
    cudaGetSymbolAddress((void**)&ge,  g_gemb);
    cudaGetSymbolAddress((void**)&r1b, g_r1);
    cudaGetSymbolAddress((void**)&r2b, g_r2);
    cudaGetSymbolAddress((void**)&sf,  g_sf);
    cudaGetSymbolAddress((void**)&ss,  g_ss);
    cudaGetSymbolAddress((void**)&cnt, g_cnt);

    cudaFuncSetAttribute(pq_hmma_kernel, cudaFuncAttributeMaxDynamicSharedMemorySize, SMEM_PQMMA);
    cudaFuncSetAttribute(edge_mma_kernel, cudaFuncAttributeMaxDynamicSharedMemorySize, SMEM_EDGE);

    // one-time per launch: prep W images + counting sort of edges by dest
    prep_w_kernel<<<24, 512>>>(Wg, Wm);
    cudaMemsetAsync(cnt, 0, (size_t)(N + 1) * sizeof(int));
    hist_kernel<<<(E + 255) / 256, 256>>>(snd, E);
    int nb = (N + SCAN_B - 1) / SCAN_B;
    scan1_kernel<<<nb, SCAN_B>>>(N);
    scan2_kernel<<<1, 512>>>(nb);
    scan3_kernel<<<nb, SCAN_B>>>(N);
    scatter_sort_kernel<<<(E + 255) / 256, 256>>>(fst, snd, E);

    const float* src = x;
    float* bufs[2] = { ls0, ls1 };
    for (int t = 0; t < 4; ++t) {
        float* dst = bufs[t & 1];
        pq_hmma_kernel<<<(N + 127) / 128, 256, SMEM_PQMMA>>>(src, pq, dst, N);
        edge_mma_kernel<<<(E + 127) / 128, 256, SMEM_EDGE>>>(pq, sf, ss, bm, bg, dst, E);
        src = dst;
    }

    gemb_kernel<<<G, 256>>>(src, gid, ge, N);
    r1_kernel<<<G, 256>>>(ge, Wr1, br1, r1b);
    r2_kernel<<<G, 256>>>(r1b, Wr2, br2, r2b);
    r3_kernel<<<G, 256>>>(r2b, Wr3, br3, (float*)d_out);
}